// round 2
// baseline (speedup 1.0000x reference)
#include <cuda_runtime.h>
#include <cuda_bf16.h>
#include <cstdint>
#include <math.h>

// SparseGate: B=16384, D=2048, E=64, K=2
//   clean = x @ gw^T ; noisy_std = softplus(x @ nw^T)
//   e = clean + noise * noisy_std ; top-2 -> softmax over 2 -> dense scatter [B,64]
//
// GEMM [16384,2048] x [2048,128] via mma.sync m16n8k8 tf32, 3-pass hi/lo split
// (near-fp32 accuracy; top-k selection-safe). Fully fused epilogue per CTA tile.

#define BDIM  2048
#define EN    64
#define NN    128            // gate(64) || noise(64) weight rows
#define BM    128
#define BK    32
#define NKT   (BDIM / BK)    // 64
#define ALD   36             // A smem lead (floats)
#define WLD   80             // W smem lead (floats): LDS.128 conflict-free
#define LLD   131            // logits smem lead (odd -> conflict-free row walk)
#define A_ST  (BM * ALD)     // 4608 floats
#define W_ST  (NN * WLD)     // 10240 floats
#define STAGE_FL (A_ST + W_ST)           // 14848 floats
#define SMEM_BYTES (3 * STAGE_FL * 4)    // 178176 B (also covers 128*131*4 logits)

// Pre-split W, tf32 hi/lo, interleaved so one LDS.128 fetches a full B-pair:
// g_Wc[n][kb][qc][0..3] = { wh(kb*8+qc), wh(kb*8+qc+4), wl(kb*8+qc), wl(kb*8+qc+4) }
__device__ float g_Wc[(size_t)NN * (BDIM * 2)];

__device__ __forceinline__ unsigned f2tf(float x) {
    unsigned r;
    asm("cvt.rna.tf32.f32 %0, %1;" : "=r"(r) : "f"(x));
    return r;
}

__device__ __forceinline__ void mma8(float* c, const unsigned* a, unsigned b0, unsigned b1) {
    asm volatile(
        "mma.sync.aligned.m16n8k8.row.col.f32.tf32.tf32.f32 "
        "{%0,%1,%2,%3},{%4,%5,%6,%7},{%8,%9},{%0,%1,%2,%3};\n"
        : "+f"(c[0]), "+f"(c[1]), "+f"(c[2]), "+f"(c[3])
        : "r"(a[0]), "r"(a[1]), "r"(a[2]), "r"(a[3]), "r"(b0), "r"(b1));
}

__device__ __forceinline__ void cp16(float* s, const float* g) {
    unsigned ss = (unsigned)__cvta_generic_to_shared(s);
    asm volatile("cp.async.cg.shared.global [%0], [%1], 16;\n" :: "r"(ss), "l"(g));
}

// ---------------- W split kernel (1 MB -> 2 MB once per launch) ----------------
__global__ void __launch_bounds__(256) split_w_kernel(const float* __restrict__ gw,
                                                      const float* __restrict__ nw) {
    int i = blockIdx.x * blockDim.x + threadIdx.x;   // (n, kb, qc)
    if (i >= NN * 256 * 4) return;
    int qc = i & 3;
    int kb = (i >> 2) & 255;
    int n  = i >> 10;
    const float* src = (n < EN) ? (gw + (size_t)n * BDIM) : (nw + (size_t)(n - EN) * BDIM);
    int k0 = kb * 8 + qc;
    float w0 = src[k0], w1 = src[k0 + 4];
    unsigned h0 = f2tf(w0); float h0f = __uint_as_float(h0);
    unsigned l0 = f2tf(w0 - h0f);
    unsigned h1 = f2tf(w1); float h1f = __uint_as_float(h1);
    unsigned l1 = f2tf(w1 - h1f);
    float4 v = make_float4(h0f, h1f, __uint_as_float(l0), __uint_as_float(l1));
    *(float4*)(g_Wc + (size_t)n * (BDIM * 2) + kb * 16 + qc * 4) = v;
}

// ---------------- fused GEMM + gate kernel ----------------
__global__ void __launch_bounds__(256, 1)
gate_kernel(const float* __restrict__ x, const float* __restrict__ noise,
            float* __restrict__ out) {
    extern __shared__ float sm[];
    const int tid  = threadIdx.x;
    const int wid  = tid >> 5, lane = tid & 31;
    const int gr   = lane >> 2, qc = lane & 3;
    const int wm   = wid & 3;        // warp row group (32 rows each)
    const int wn   = wid >> 2;       // warp col group (64 cols each)
    const int m0   = blockIdx.x * BM;

    float acc[2][8][4];
#pragma unroll
    for (int a = 0; a < 2; a++)
#pragma unroll
        for (int b = 0; b < 8; b++)
#pragma unroll
            for (int c = 0; c < 4; c++) acc[a][b][c] = 0.f;

    auto load_stage = [&](int kt, int s) {
        float* As = sm + s * STAGE_FL;
        float* Ws = As + A_ST;
        int k0 = kt * BK;
#pragma unroll
        for (int i = 0; i < 4; i++) {                 // A tile: 128 x 32 f32 = 16 KB
            int idx = tid + i * 256;                  // 0..1023
            int row = idx >> 3, c = (idx & 7) * 4;
            cp16(As + row * ALD + c, x + (size_t)(m0 + row) * BDIM + k0 + c);
        }
#pragma unroll
        for (int i = 0; i < 8; i++) {                 // W tile: 128n x 64 floats = 32 KB
            int idx = tid + i * 256;                  // 0..2047
            int n = idx >> 4, ch = idx & 15;
            cp16(Ws + n * WLD + ch * 4, g_Wc + (size_t)n * (BDIM * 2) + kt * 64 + ch * 4);
        }
    };

    load_stage(0, 0); asm volatile("cp.async.commit_group;\n" ::: "memory");
    load_stage(1, 1); asm volatile("cp.async.commit_group;\n" ::: "memory");

    for (int kt = 0; kt < NKT; kt++) {
        asm volatile("cp.async.wait_group 1;\n" ::: "memory");
        __syncthreads();
        if (kt + 2 < NKT) load_stage(kt + 2, (kt + 2) % 3);
        asm volatile("cp.async.commit_group;\n" ::: "memory");

        const float* As = sm + (kt % 3) * STAGE_FL;
        const float* Ws = As + A_ST;
#pragma unroll
        for (int kk = 0; kk < 4; kk++) {
            unsigned ah[2][4], al[2][4];
#pragma unroll
            for (int tm = 0; tm < 2; tm++) {
                int r0 = 32 * wm + 16 * tm + gr;
                float v0 = As[r0 * ALD + kk * 8 + qc];
                float v1 = As[(r0 + 8) * ALD + kk * 8 + qc];
                float v2 = As[r0 * ALD + kk * 8 + qc + 4];
                float v3 = As[(r0 + 8) * ALD + kk * 8 + qc + 4];
                ah[tm][0] = f2tf(v0); al[tm][0] = f2tf(v0 - __uint_as_float(ah[tm][0]));
                ah[tm][1] = f2tf(v1); al[tm][1] = f2tf(v1 - __uint_as_float(ah[tm][1]));
                ah[tm][2] = f2tf(v2); al[tm][2] = f2tf(v2 - __uint_as_float(ah[tm][2]));
                ah[tm][3] = f2tf(v3); al[tm][3] = f2tf(v3 - __uint_as_float(ah[tm][3]));
            }
#pragma unroll
            for (int t = 0; t < 8; t++) {
                int nb = 64 * wn + 8 * t + gr;
                const float4 bv = *(const float4*)(Ws + nb * WLD + kk * 16 + qc * 4);
                unsigned b0h = __float_as_uint(bv.x), b1h = __float_as_uint(bv.y);
                unsigned b0l = __float_as_uint(bv.z), b1l = __float_as_uint(bv.w);
#pragma unroll
                for (int tm = 0; tm < 2; tm++) {
                    mma8(acc[tm][t], ah[tm], b0h, b1h);   // hi*hi
                    mma8(acc[tm][t], ah[tm], b0l, b1l);   // hi*lo
                    mma8(acc[tm][t], al[tm], b0h, b1h);   // lo*hi
                }
            }
        }
    }

    // ------------- epilogue -------------
    asm volatile("cp.async.wait_group 0;\n" ::: "memory");
    __syncthreads();                 // all warps done reading stage smem
    float* Ls = sm;                  // reuse smem: [128][LLD] logits
#pragma unroll
    for (int tm = 0; tm < 2; tm++) {
        int rb = 32 * wm + 16 * tm;
#pragma unroll
        for (int t = 0; t < 8; t++) {
            int col = 64 * wn + 8 * t + qc * 2;
            Ls[(rb + gr)     * LLD + col]     = acc[tm][t][0];
            Ls[(rb + gr)     * LLD + col + 1] = acc[tm][t][1];
            Ls[(rb + gr + 8) * LLD + col]     = acc[tm][t][2];
            Ls[(rb + gr + 8) * LLD + col + 1] = acc[tm][t][3];
        }
    }
    __syncthreads();

    // zero this CTA's output block (coalesced)
    {
        float4 z4 = make_float4(0.f, 0.f, 0.f, 0.f);
        float4* ob = (float4*)(out + (size_t)m0 * EN);
#pragma unroll
        for (int i = tid; i < BM * EN / 4; i += 256) ob[i] = z4;
    }

    // per-row softplus + noisy combine + top-2 + softmax (128 threads, one row each)
    int   bi = 0, si = 0;
    float p1 = 0.f, p2 = 0.f;
    if (tid < BM) {
        const float* Lr = Ls + tid * LLD;
        const float* nz = noise + (size_t)(m0 + tid) * EN;
        float best = -1e30f, second = -1e30f;
#pragma unroll 4
        for (int e = 0; e < EN; e++) {
            float z  = Lr[EN + e];
            float sp = fmaxf(z, 0.f) + log1pf(expf(-fabsf(z)));   // accurate softplus
            float w  = Lr[e] + nz[e] * sp;
            if (w > best)        { second = best; si = bi; best = w; bi = e; }
            else if (w > second) { second = w; si = e; }
        }
        float e2  = expf(second - best);      // <= 1
        float inv = 1.f / (1.f + e2);
        p1 = inv; p2 = e2 * inv;
    }
    __syncthreads();                          // order scatter after zero-fill
    if (tid < BM) {
        float* orow = out + (size_t)(m0 + tid) * EN;
        orow[bi] = p1;
        orow[si] = p2;
    }
}

extern "C" void kernel_launch(void* const* d_in, const int* in_sizes, int n_in,
                              void* d_out, int out_size) {
    const float* x  = (const float*)d_in[0];
    const float* gw = (const float*)d_in[1];
    const float* nw = (const float*)d_in[2];
    const float* nz = (const float*)d_in[3];
    float* out = (float*)d_out;

    static bool attr_done = false;   // attribute set is idempotent & deterministic
    if (!attr_done) {
        cudaFuncSetAttribute(gate_kernel, cudaFuncAttributeMaxDynamicSharedMemorySize,
                             SMEM_BYTES);
        attr_done = true;
    }

    split_w_kernel<<<(NN * 1024 + 255) / 256, 256>>>(gw, nw);
    gate_kernel<<<BM == 128 ? 128 : 128, 256, SMEM_BYTES>>>(x, nz, out);
}

// round 4
// speedup vs baseline: 1.5060x; 1.5060x over previous
#include <cuda_runtime.h>
#include <cuda_fp16.h>
#include <cstdint>
#include <math.h>

// SparseGate: B=16384, D=2048, E=64, K=2
// mma.sync.m16n8k16.f16 (f32 accum), 3-pass hi/lo split (hh+hl+lh).
// W pre-scaled x1024 so lo-half stays fp16-normal; epilogue undoes scale.
// Fused softplus + noisy combine + top-2 + softmax + dense scatter.

#define BDIM 2048
#define EN   64
#define NN   128          // gate(64) || noise(64)
#define BM   128
#define BK   32
#define NKT  (BDIM / BK)  // 64
#define WSCALE 1024.0f
#define WSCALE_INV 0.0009765625f
#define LLD  131

// stage layout (bytes): A-hi [128 rows x 80B], A-lo same, W [128 cols x 192B]
#define ST_AH 0
#define ST_AL 10240
#define ST_W  20480
#define STAGE 45056
#define SMEM_TOTAL (3 * STAGE)   // 135168

// Pre-split W records: per (ktile, n, kc, qc) a 16B record
// { wh[2qc],wh[2qc+1], wh[2qc+8],wh[2qc+9], wl[...same 4] }  (fp16, k rel to ktile*32+kc*16)
__device__ uint4 g_Wc[(size_t)NKT * 1024];   // 64 ktiles * 128 n * 8 records

__device__ __forceinline__ uint32_t smem_u32(const void* p) {
    uint32_t a;
    asm("{ .reg .u64 t; cvta.to.shared.u64 t, %1; cvt.u32.u64 %0, t; }" : "=r"(a) : "l"(p));
    return a;
}
__device__ __forceinline__ void cp16(uint32_t saddr, const void* g) {
    asm volatile("cp.async.cg.shared.global [%0], [%1], 16;" :: "r"(saddr), "l"(g));
}
__device__ __forceinline__ void ldm4(uint32_t* r, uint32_t addr) {
    asm volatile("ldmatrix.sync.aligned.m8n8.x4.shared.b16 {%0,%1,%2,%3}, [%4];"
                 : "=r"(r[0]), "=r"(r[1]), "=r"(r[2]), "=r"(r[3]) : "r"(addr));
}
__device__ __forceinline__ void lds128(uint32_t* r, uint32_t addr) {
    asm volatile("ld.shared.v4.b32 {%0,%1,%2,%3}, [%4];"
                 : "=r"(r[0]), "=r"(r[1]), "=r"(r[2]), "=r"(r[3]) : "r"(addr));
}
__device__ __forceinline__ void sts128(uint32_t addr, uint32_t a, uint32_t b,
                                       uint32_t c, uint32_t d) {
    asm volatile("st.shared.v4.b32 [%0], {%1,%2,%3,%4};"
                 :: "r"(addr), "r"(a), "r"(b), "r"(c), "r"(d) : "memory");
}
__device__ __forceinline__ void mma16(float* c, const uint32_t* a, uint32_t b0, uint32_t b1) {
    asm volatile("mma.sync.aligned.m16n8k16.row.col.f32.f16.f16.f32 "
                 "{%0,%1,%2,%3},{%4,%5,%6,%7},{%8,%9},{%0,%1,%2,%3};\n"
                 : "+f"(c[0]), "+f"(c[1]), "+f"(c[2]), "+f"(c[3])
                 : "r"(a[0]), "r"(a[1]), "r"(a[2]), "r"(a[3]), "r"(b0), "r"(b1));
}
// pack two floats to half2 (lo-first), return rounding residuals
__device__ __forceinline__ uint32_t pack2(float a, float b, float& ra, float& rb) {
    __half ha = __float2half_rn(a), hb = __float2half_rn(b);
    ra = a - __half2float(ha);
    rb = b - __half2float(hb);
    __half2 p = __halves2half2(ha, hb);
    return *reinterpret_cast<uint32_t*>(&p);
}

// ---------------- W pre-split ----------------
__global__ void __launch_bounds__(256) split_w_kernel(const float* __restrict__ gw,
                                                      const float* __restrict__ nw) {
    int i = blockIdx.x * blockDim.x + threadIdx.x;   // (n, kt, kc, qc)
    if (i >= NN * NKT * 8) return;
    int qc = i & 3, kc = (i >> 2) & 1, kt = (i >> 3) & 63, n = i >> 9;
    const float* src = (n < EN) ? (gw + (size_t)n * BDIM) : (nw + (size_t)(n - EN) * BDIM);
    int kb = kt * BK + kc * 16 + 2 * qc;
    float w0 = src[kb] * WSCALE,     w1 = src[kb + 1] * WSCALE;
    float w2 = src[kb + 8] * WSCALE, w3 = src[kb + 9] * WSCALE;
    float r0, r1, r2, r3;
    uint32_t h01 = pack2(w0, w1, r0, r1);
    uint32_t h23 = pack2(w2, w3, r2, r3);
    float d0, d1;
    uint32_t l01 = pack2(r0, r1, d0, d1);
    uint32_t l23 = pack2(r2, r3, d0, d1);
    g_Wc[(size_t)kt * 1024 + n * 8 + kc * 4 + qc] = make_uint4(h01, h23, l01, l23);
}

// ---------------- fused GEMM + gate ----------------
__global__ void __launch_bounds__(512, 1)
gate_kernel(const float* __restrict__ x, const float* __restrict__ noise,
            float* __restrict__ out) {
    extern __shared__ char smem[];
    const uint32_t sb = smem_u32(smem);
    const int tid  = threadIdx.x;
    const int wid  = tid >> 5, lane = tid & 31;
    const int gr   = lane >> 2, qc = lane & 3;
    const int wm   = wid & 3;         // 4 row groups of 32
    const int wn   = wid >> 2;        // 4 col groups of 32
    const int m0   = blockIdx.x * BM;

    // A staging ids: this thread stores row ar, octet ao (8 k-values)
    const int ar = tid & 127, ao = tid >> 7;
    const float* xrow = x + (size_t)(m0 + ar) * BDIM + ao * 8;

    // ldmatrix lane address components
    const int lrow = (lane & 7) + ((lane >> 3) & 1) * 8;   // 0..15
    const int lko  = (lane >> 4) * 8;                      // 0 or 8
    const uint32_t abase = (uint32_t)((32 * wm + lrow) * 80 + lko * 2);
    const uint32_t wbase = (uint32_t)((32 * wn + gr) * 192 + qc * 16);

    float acc[2][4][4];
#pragma unroll
    for (int a = 0; a < 2; a++)
#pragma unroll
        for (int b = 0; b < 4; b++)
#pragma unroll
            for (int c = 0; c < 4; c++) acc[a][b][c] = 0.f;

    auto copyW = [&](int kt, uint32_t stage) {
#pragma unroll
        for (int j = 0; j < 2; j++) {
            int id = tid + j * 512;                        // 1024 records
            cp16(stage + ST_W + (id >> 3) * 192 + (id & 7) * 16,
                 (const void*)(g_Wc + (size_t)kt * 1024 + id));
        }
    };
    auto stsA = [&](uint32_t stage, float4 v0, float4 v1) {
        float r0, r1, r2, r3, r4, r5, r6, r7;
        uint32_t h0 = pack2(v0.x, v0.y, r0, r1);
        uint32_t h1 = pack2(v0.z, v0.w, r2, r3);
        uint32_t h2 = pack2(v1.x, v1.y, r4, r5);
        uint32_t h3 = pack2(v1.z, v1.w, r6, r7);
        float d0, d1;
        uint32_t l0 = pack2(r0, r1, d0, d1);
        uint32_t l1 = pack2(r2, r3, d0, d1);
        uint32_t l2 = pack2(r4, r5, d0, d1);
        uint32_t l3 = pack2(r6, r7, d0, d1);
        uint32_t base = stage + (uint32_t)(ar * 80 + ao * 16);
        sts128(base + ST_AH, h0, h1, h2, h3);
        sts128(base + ST_AL, l0, l1, l2, l3);
    };

    // prolog
    copyW(0, sb + 0 * STAGE);
    asm volatile("cp.async.commit_group;" ::: "memory");
    copyW(1, sb + 1 * STAGE);
    asm volatile("cp.async.commit_group;" ::: "memory");
    {
        float4 v0 = *(const float4*)(xrow);
        float4 v1 = *(const float4*)(xrow + 4);
        stsA(sb + 0 * STAGE, v0, v1);                      // A(0)
    }
    float4 xr0 = *(const float4*)(xrow + BK);              // A(1) regs
    float4 xr1 = *(const float4*)(xrow + BK + 4);

    for (int kt = 0; kt < NKT; kt++) {
        const uint32_t stg = sb + (kt % 3) * STAGE;
        asm volatile("cp.async.wait_group 1;" ::: "memory");   // W(kt) landed
        __syncthreads();                                       // A(kt)+W(kt) visible

        if (kt + 1 < NKT)
            stsA(sb + ((kt + 1) % 3) * STAGE, xr0, xr1);       // convert & stage A(kt+1)
        if (kt + 2 < NKT) {
            const float* xp = xrow + (kt + 2) * BK;
            xr0 = *(const float4*)(xp);
            xr1 = *(const float4*)(xp + 4);
            copyW(kt + 2, sb + ((kt + 2) % 3) * STAGE);
        }
        asm volatile("cp.async.commit_group;" ::: "memory");

#pragma unroll
        for (int kc = 0; kc < 2; kc++) {
            uint32_t ah[2][4], al[2][4];
            ldm4(ah[0], stg + ST_AH + abase + kc * 32);
            ldm4(ah[1], stg + ST_AH + abase + 1280 + kc * 32);
            ldm4(al[0], stg + ST_AL + abase + kc * 32);
            ldm4(al[1], stg + ST_AL + abase + 1280 + kc * 32);
            uint32_t bh[4][2], bl[4][2];
#pragma unroll
            for (int t = 0; t < 4; t++) {
                uint32_t r[4];
                lds128(r, stg + ST_W + wbase + t * 1536 + kc * 64);
                bh[t][0] = r[0]; bh[t][1] = r[1];
                bl[t][0] = r[2]; bl[t][1] = r[3];
            }
            // pass-major issue order: 8 independent MMAs per pass
#pragma unroll
            for (int t = 0; t < 4; t++) {
                mma16(acc[0][t], ah[0], bh[t][0], bh[t][1]);
                mma16(acc[1][t], ah[1], bh[t][0], bh[t][1]);
            }
#pragma unroll
            for (int t = 0; t < 4; t++) {
                mma16(acc[0][t], ah[0], bl[t][0], bl[t][1]);
                mma16(acc[1][t], ah[1], bl[t][0], bl[t][1]);
            }
#pragma unroll
            for (int t = 0; t < 4; t++) {
                mma16(acc[0][t], al[0], bh[t][0], bh[t][1]);
                mma16(acc[1][t], al[1], bh[t][0], bh[t][1]);
            }
        }
    }

    // -------- epilogue --------
    __syncthreads();                 // all warps done reading stages
    float* Ls = (float*)smem;        // [128][LLD] logits (reuses stage smem)
#pragma unroll
    for (int tm = 0; tm < 2; tm++) {
        int row0 = 32 * wm + 16 * tm + gr;
#pragma unroll
        for (int t = 0; t < 4; t++) {
            int col0 = 32 * wn + 8 * t + 2 * qc;
            Ls[row0 * LLD + col0]           = acc[tm][t][0] * WSCALE_INV;
            Ls[row0 * LLD + col0 + 1]       = acc[tm][t][1] * WSCALE_INV;
            Ls[(row0 + 8) * LLD + col0]     = acc[tm][t][2] * WSCALE_INV;
            Ls[(row0 + 8) * LLD + col0 + 1] = acc[tm][t][3] * WSCALE_INV;
        }
    }
    // zero this CTA's output block (coalesced) while Ls settles
    {
        float4 z = make_float4(0.f, 0.f, 0.f, 0.f);
        float4* ob = (float4*)(out + (size_t)m0 * EN);
#pragma unroll
        for (int i = tid; i < BM * EN / 4; i += 512) ob[i] = z;
    }
    __syncthreads();

    if (tid < BM) {                  // one output row per thread
        const float* Lr = Ls + tid * LLD;
        const float* nz = noise + (size_t)(m0 + tid) * EN;
        float best = -3e38f, second = -3e38f;
        int bi = 0, si = 0;
#pragma unroll 4
        for (int e = 0; e < EN; e++) {
            float z  = Lr[EN + e];
            float sp = fmaxf(z, 0.f) + log1pf(expf(-fabsf(z)));   // accurate softplus
            float w  = Lr[e] + nz[e] * sp;
            if (w > best)        { second = best; si = bi; best = w; bi = e; }
            else if (w > second) { second = w; si = e; }
        }
        float e2  = expf(second - best);
        float inv = 1.f / (1.f + e2);
        float* orow = out + (size_t)(m0 + tid) * EN;
        orow[bi] = inv;
        orow[si] = e2 * inv;
    }
}

extern "C" void kernel_launch(void* const* d_in, const int* in_sizes, int n_in,
                              void* d_out, int out_size) {
    const float* x  = (const float*)d_in[0];
    const float* gw = (const float*)d_in[1];
    const float* nw = (const float*)d_in[2];
    const float* nz = (const float*)d_in[3];
    float* out = (float*)d_out;

    static bool attr_done = false;
    if (!attr_done) {
        cudaFuncSetAttribute(gate_kernel, cudaFuncAttributeMaxDynamicSharedMemorySize,
                             SMEM_TOTAL);
        attr_done = true;
    }

    split_w_kernel<<<(NN * NKT * 8 + 255) / 256, 256>>>(gw, nw);
    gate_kernel<<<16384 / BM, 512, SMEM_TOTAL>>>(x, nz, out);
}

// round 6
// speedup vs baseline: 1.5369x; 1.0205x over previous
#include <cuda_runtime.h>
#include <cuda_fp16.h>
#include <cstdint>
#include <math.h>

// SparseGate: B=16384, D=2048, E=64, K=2
// mma.sync.m16n8k16.f16 (f32 accum), 3-pass hi/lo split (hh+hl+lh).
// W pre-scaled x1024 so lo-half stays fp16-normal; epilogue undoes scale.
// 16 warps = 4(wm) x 2(wn) x 2(kg split-K); warp tile 32x64, SW64 A staging.
// B fragments processed in 2 halves of 4 n-tiles to stay under 128 regs.

#define BDIM 2048
#define EN   64
#define NN   128          // gate(64) || noise(64)
#define BM   128
#define BK   32
#define NKT  (BDIM / BK)  // 64
#define WSCALE 1024.0f
#define WSCALE_INV 0.0009765625f
#define LLD  131

// stage layout (bytes): A-hi [128 x 64B SW64], A-lo same, W [128 cols x 192B]
#define ST_AH 0
#define ST_AL 8192
#define ST_W  16384
#define STAGE 40960
#define SMEM_TOTAL (3 * STAGE)   // 122880 (>= 128*131*4 = 67072 for logits)

#define SW64(o) ((o) ^ (((o) >> 3) & 0x30))

// Pre-split W records: per (ktile, n, kc, qc) a 16B record
// { wh[2qc],wh[2qc+1], wh[2qc+8],wh[2qc+9], wl[same 4] } (fp16)
__device__ uint4 g_Wc[(size_t)NKT * 1024];   // 64 ktiles * 128 n * 8 records

__device__ __forceinline__ uint32_t smem_u32(const void* p) {
    uint32_t a;
    asm("{ .reg .u64 t; cvta.to.shared.u64 t, %1; cvt.u32.u64 %0, t; }" : "=r"(a) : "l"(p));
    return a;
}
__device__ __forceinline__ void cp16(uint32_t saddr, const void* g) {
    asm volatile("cp.async.cg.shared.global [%0], [%1], 16;" :: "r"(saddr), "l"(g));
}
__device__ __forceinline__ void ldm4(uint32_t* r, uint32_t addr) {
    asm volatile("ldmatrix.sync.aligned.m8n8.x4.shared.b16 {%0,%1,%2,%3}, [%4];"
                 : "=r"(r[0]), "=r"(r[1]), "=r"(r[2]), "=r"(r[3]) : "r"(addr));
}
__device__ __forceinline__ void lds128(uint32_t* r, uint32_t addr) {
    asm volatile("ld.shared.v4.b32 {%0,%1,%2,%3}, [%4];"
                 : "=r"(r[0]), "=r"(r[1]), "=r"(r[2]), "=r"(r[3]) : "r"(addr));
}
__device__ __forceinline__ void sts128(uint32_t addr, uint32_t a, uint32_t b,
                                       uint32_t c, uint32_t d) {
    asm volatile("st.shared.v4.b32 [%0], {%1,%2,%3,%4};"
                 :: "r"(addr), "r"(a), "r"(b), "r"(c), "r"(d) : "memory");
}
__device__ __forceinline__ void mma16(float* c, const uint32_t* a, uint32_t b0, uint32_t b1) {
    asm volatile("mma.sync.aligned.m16n8k16.row.col.f32.f16.f16.f32 "
                 "{%0,%1,%2,%3},{%4,%5,%6,%7},{%8,%9},{%0,%1,%2,%3};\n"
                 : "+f"(c[0]), "+f"(c[1]), "+f"(c[2]), "+f"(c[3])
                 : "r"(a[0]), "r"(a[1]), "r"(a[2]), "r"(a[3]), "r"(b0), "r"(b1));
}
__device__ __forceinline__ uint32_t pack2(float a, float b, float& ra, float& rb) {
    __half ha = __float2half_rn(a), hb = __float2half_rn(b);
    ra = a - __half2float(ha);
    rb = b - __half2float(hb);
    __half2 p = __halves2half2(ha, hb);
    return *reinterpret_cast<uint32_t*>(&p);
}

// ---------------- W pre-split ----------------
__global__ void __launch_bounds__(256) split_w_kernel(const float* __restrict__ gw,
                                                      const float* __restrict__ nw) {
    int i = blockIdx.x * blockDim.x + threadIdx.x;   // (n, kt, kc, qc)
    if (i >= NN * NKT * 8) return;
    int qc = i & 3, kc = (i >> 2) & 1, kt = (i >> 3) & 63, n = i >> 9;
    const float* src = (n < EN) ? (gw + (size_t)n * BDIM) : (nw + (size_t)(n - EN) * BDIM);
    int kb = kt * BK + kc * 16 + 2 * qc;
    float w0 = src[kb] * WSCALE,     w1 = src[kb + 1] * WSCALE;
    float w2 = src[kb + 8] * WSCALE, w3 = src[kb + 9] * WSCALE;
    float r0, r1, r2, r3;
    uint32_t h01 = pack2(w0, w1, r0, r1);
    uint32_t h23 = pack2(w2, w3, r2, r3);
    float d0, d1;
    uint32_t l01 = pack2(r0, r1, d0, d1);
    uint32_t l23 = pack2(r2, r3, d0, d1);
    g_Wc[(size_t)kt * 1024 + n * 8 + kc * 4 + qc] = make_uint4(h01, h23, l01, l23);
}

// ---------------- fused GEMM + gate ----------------
__global__ void __launch_bounds__(512, 1)
gate_kernel(const float* __restrict__ x, const float* __restrict__ noise,
            float* __restrict__ out) {
    extern __shared__ char smem[];
    const uint32_t sb = smem_u32(smem);
    const int tid  = threadIdx.x;
    const int wid  = tid >> 5, lane = tid & 31;
    const int gr   = lane >> 2, qc = lane & 3;
    const int wm   = wid & 3;          // 4 row groups of 32
    const int wn   = (wid >> 2) & 1;   // 2 col groups of 64
    const int kg   = wid >> 3;         // split-K half (kc index)
    const int m0   = blockIdx.x * BM;

    // A staging: this thread stores row ar, k-octet ao (8 fp32 -> 16B fp16)
    const int ar = tid & 127, ao = tid >> 7;
    const float* xrow = x + (size_t)(m0 + ar) * BDIM + ao * 8;
    const uint32_t swoA = SW64((uint32_t)(ar * 64 + ao * 16));

    // ldmatrix addresses (tile-relative, SW64), for tm=0,1 sub-tiles of 16 rows
    const int lrow = lane & 15, lko = lane >> 4;   // row 0..15, k-octet 0..1
    uint32_t aoff[2];
#pragma unroll
    for (int tm = 0; tm < 2; tm++)
        aoff[tm] = SW64((uint32_t)((32 * wm + 16 * tm + lrow) * 64 + kg * 32 + lko * 16));
    // B fragment base: record n*192 + kc*64 + qc*16
    const uint32_t wbase = (uint32_t)((64 * wn + gr) * 192 + kg * 64 + qc * 16);

    float acc[2][8][4];
#pragma unroll
    for (int a = 0; a < 2; a++)
#pragma unroll
        for (int b = 0; b < 8; b++)
#pragma unroll
            for (int c = 0; c < 4; c++) acc[a][b][c] = 0.f;

    auto copyW = [&](int kt, uint32_t stage) {
#pragma unroll
        for (int j = 0; j < 2; j++) {
            int id = tid + j * 512;                        // 1024 records
            cp16(stage + ST_W + (id >> 3) * 192 + (id & 7) * 16,
                 (const void*)(g_Wc + (size_t)kt * 1024 + id));
        }
    };
    auto stsA = [&](uint32_t stage, float4 v0, float4 v1) {
        float r0, r1, r2, r3, r4, r5, r6, r7;
        uint32_t h0 = pack2(v0.x, v0.y, r0, r1);
        uint32_t h1 = pack2(v0.z, v0.w, r2, r3);
        uint32_t h2 = pack2(v1.x, v1.y, r4, r5);
        uint32_t h3 = pack2(v1.z, v1.w, r6, r7);
        float d0, d1;
        uint32_t l0 = pack2(r0, r1, d0, d1);
        uint32_t l1 = pack2(r2, r3, d0, d1);
        uint32_t l2 = pack2(r4, r5, d0, d1);
        uint32_t l3 = pack2(r6, r7, d0, d1);
        sts128(stage + ST_AH + swoA, h0, h1, h2, h3);
        sts128(stage + ST_AL + swoA, l0, l1, l2, l3);
    };

    // prolog
    copyW(0, sb + 0 * STAGE);
    asm volatile("cp.async.commit_group;" ::: "memory");
    copyW(1, sb + 1 * STAGE);
    asm volatile("cp.async.commit_group;" ::: "memory");
    {
        float4 v0 = *(const float4*)(xrow);
        float4 v1 = *(const float4*)(xrow + 4);
        stsA(sb + 0 * STAGE, v0, v1);                      // A(0)
    }
    float4 xr0 = *(const float4*)(xrow + BK);              // A(1) regs
    float4 xr1 = *(const float4*)(xrow + BK + 4);

    for (int kt = 0; kt < NKT; kt++) {
        const uint32_t stg = sb + (kt % 3) * STAGE;
        asm volatile("cp.async.wait_group 1;" ::: "memory");   // W(kt) landed
        __syncthreads();                                       // A(kt)+W(kt) visible

        if (kt + 1 < NKT)
            stsA(sb + ((kt + 1) % 3) * STAGE, xr0, xr1);       // convert & stage A(kt+1)
        if (kt + 2 < NKT) {
            const float* xp = xrow + (kt + 2) * BK;
            xr0 = *(const float4*)(xp);
            xr1 = *(const float4*)(xp + 4);
            copyW(kt + 2, sb + ((kt + 2) % 3) * STAGE);
        }
        asm volatile("cp.async.commit_group;" ::: "memory");

        // this warp computes only its kc = kg half (split-K)
        uint32_t ah[2][4], al[2][4];
        ldm4(ah[0], stg + ST_AH + aoff[0]);
        ldm4(ah[1], stg + ST_AH + aoff[1]);
        ldm4(al[0], stg + ST_AL + aoff[0]);
        ldm4(al[1], stg + ST_AL + aoff[1]);

        // two halves of 4 n-tiles: keeps b-frag regs at 16, dep distance 8
#pragma unroll
        for (int th = 0; th < 2; th++) {
            uint32_t bh[4][2], bl[4][2];
#pragma unroll
            for (int t = 0; t < 4; t++) {
                uint32_t r[4];
                lds128(r, stg + ST_W + wbase + (th * 4 + t) * 1536);
                bh[t][0] = r[0]; bh[t][1] = r[1];
                bl[t][0] = r[2]; bl[t][1] = r[3];
            }
#pragma unroll
            for (int t = 0; t < 4; t++) {                      // hh pass
                mma16(acc[0][th * 4 + t], ah[0], bh[t][0], bh[t][1]);
                mma16(acc[1][th * 4 + t], ah[1], bh[t][0], bh[t][1]);
            }
#pragma unroll
            for (int t = 0; t < 4; t++) {                      // hl pass
                mma16(acc[0][th * 4 + t], ah[0], bl[t][0], bl[t][1]);
                mma16(acc[1][th * 4 + t], ah[1], bl[t][0], bl[t][1]);
            }
#pragma unroll
            for (int t = 0; t < 4; t++) {                      // lh pass
                mma16(acc[0][th * 4 + t], al[0], bh[t][0], bh[t][1]);
                mma16(acc[1][th * 4 + t], al[1], bh[t][0], bh[t][1]);
            }
        }
    }

    // -------- epilogue --------
    __syncthreads();                 // all warps done reading stages
    float* Ls = (float*)smem;        // [128][LLD] logits (reuses stage smem)
    // kg=0 warps write their partial sums (scaled)
    if (kg == 0) {
#pragma unroll
        for (int tm = 0; tm < 2; tm++) {
            int row0 = 32 * wm + 16 * tm + gr;
#pragma unroll
            for (int t = 0; t < 8; t++) {
                int col0 = 64 * wn + 8 * t + 2 * qc;
                Ls[row0 * LLD + col0]           = acc[tm][t][0] * WSCALE_INV;
                Ls[row0 * LLD + col0 + 1]       = acc[tm][t][1] * WSCALE_INV;
                Ls[(row0 + 8) * LLD + col0]     = acc[tm][t][2] * WSCALE_INV;
                Ls[(row0 + 8) * LLD + col0 + 1] = acc[tm][t][3] * WSCALE_INV;
            }
        }
    }
    // zero this CTA's output block (coalesced) meanwhile
    {
        float4 z = make_float4(0.f, 0.f, 0.f, 0.f);
        float4* ob = (float4*)(out + (size_t)m0 * EN);
#pragma unroll
        for (int i = tid; i < BM * EN / 4; i += 512) ob[i] = z;
    }
    __syncthreads();
    // kg=1 warps add their halves
    if (kg == 1) {
#pragma unroll
        for (int tm = 0; tm < 2; tm++) {
            int row0 = 32 * wm + 16 * tm + gr;
#pragma unroll
            for (int t = 0; t < 8; t++) {
                int col0 = 64 * wn + 8 * t + 2 * qc;
                Ls[row0 * LLD + col0]           += acc[tm][t][0] * WSCALE_INV;
                Ls[row0 * LLD + col0 + 1]       += acc[tm][t][1] * WSCALE_INV;
                Ls[(row0 + 8) * LLD + col0]     += acc[tm][t][2] * WSCALE_INV;
                Ls[(row0 + 8) * LLD + col0 + 1] += acc[tm][t][3] * WSCALE_INV;
            }
        }
    }
    __syncthreads();

    if (tid < BM) {                  // one output row per thread
        const float* Lr = Ls + tid * LLD;
        const float* nz = noise + (size_t)(m0 + tid) * EN;
        float best = -3e38f, second = -3e38f;
        int bi = 0, si = 0;
#pragma unroll 4
        for (int e = 0; e < EN; e++) {
            float z  = Lr[EN + e];
            float sp = fmaxf(z, 0.f) + log1pf(expf(-fabsf(z)));   // accurate softplus
            float w  = Lr[e] + nz[e] * sp;
            if (w > best)        { second = best; si = bi; best = w; bi = e; }
            else if (w > second) { second = w; si = e; }
        }
        float e2  = expf(second - best);
        float inv = 1.f / (1.f + e2);
        float* orow = out + (size_t)(m0 + tid) * EN;
        orow[bi] = inv;
        orow[si] = e2 * inv;
    }
}

extern "C" void kernel_launch(void* const* d_in, const int* in_sizes, int n_in,
                              void* d_out, int out_size) {
    const float* x  = (const float*)d_in[0];
    const float* gw = (const float*)d_in[1];
    const float* nw = (const float*)d_in[2];
    const float* nz = (const float*)d_in[3];
    float* out = (float*)d_out;

    static bool attr_done = false;
    if (!attr_done) {
        cudaFuncSetAttribute(gate_kernel, cudaFuncAttributeMaxDynamicSharedMemorySize,
                             SMEM_TOTAL);
        attr_done = true;
    }

    split_w_kernel<<<(NN * NKT * 8 + 255) / 256, 256>>>(gw, nw);
    gate_kernel<<<16384 / BM, 512, SMEM_TOTAL>>>(x, nz, out);
}

// round 9
// speedup vs baseline: 1.6584x; 1.0790x over previous
#include <cuda_runtime.h>
#include <cuda_fp16.h>
#include <cstdint>
#include <math.h>

// SparseGate: B=16384, D=2048, E=64, K=2
// mma.sync.m16n8k16.f16 (f32 accum), 3-pass hi/lo split (hh+hl+lh).
// W pre-scaled x1024 so lo-half stays fp16-normal; epilogue undoes scale.
// 16 warps = 4(wm) x 4(wn), warp tile 32x32. Register-pipelined fragments:
// A-frags double-buffered across kc-steps, A staged 2 ktiles ahead so frag
// loads of the next ktile overlap the current MMA burst.
// NOTE: kc offset applied to swizzled A address via XOR (SW64(b+32)=SW64(b)^32).

#define BDIM 2048
#define EN   64
#define NN   128          // gate(64) || noise(64)
#define BM   128
#define BK   32
#define NKT  (BDIM / BK)  // 64
#define WSCALE 1024.0f
#define WSCALE_INV 0.0009765625f
#define LLD  131

// stage layout (bytes): A-hi [128 x 64B SW64], A-lo same, W [128 n x 192B]
#define ST_AH 0
#define ST_AL 8192
#define ST_W  16384
#define STAGE 40960
#define SMEM_TOTAL (3 * STAGE)   // 122880 (>= 128*131*4 = 67072 for logits)

#define SW64(o) ((o) ^ (((o) >> 3) & 0x30))

// Pre-split W records: per (ktile, n, kc, qc) a 16B record
// { wh[2qc],wh[2qc+1], wh[2qc+8],wh[2qc+9], wl[same 4] } (fp16)
__device__ uint4 g_Wc[(size_t)NKT * 1024];   // 64 ktiles * 128 n * 8 records

__device__ __forceinline__ uint32_t smem_u32(const void* p) {
    uint32_t a;
    asm("{ .reg .u64 t; cvta.to.shared.u64 t, %1; cvt.u32.u64 %0, t; }" : "=r"(a) : "l"(p));
    return a;
}
__device__ __forceinline__ void cp16(uint32_t saddr, const void* g) {
    asm volatile("cp.async.cg.shared.global [%0], [%1], 16;" :: "r"(saddr), "l"(g));
}
__device__ __forceinline__ void ldm4(uint32_t* r, uint32_t addr) {
    asm volatile("ldmatrix.sync.aligned.m8n8.x4.shared.b16 {%0,%1,%2,%3}, [%4];"
                 : "=r"(r[0]), "=r"(r[1]), "=r"(r[2]), "=r"(r[3]) : "r"(addr));
}
__device__ __forceinline__ void lds128(uint32_t* r, uint32_t addr) {
    asm volatile("ld.shared.v4.b32 {%0,%1,%2,%3}, [%4];"
                 : "=r"(r[0]), "=r"(r[1]), "=r"(r[2]), "=r"(r[3]) : "r"(addr));
}
__device__ __forceinline__ void sts128(uint32_t addr, uint32_t a, uint32_t b,
                                       uint32_t c, uint32_t d) {
    asm volatile("st.shared.v4.b32 [%0], {%1,%2,%3,%4};"
                 :: "r"(addr), "r"(a), "r"(b), "r"(c), "r"(d) : "memory");
}
__device__ __forceinline__ void mma16(float* c, const uint32_t* a, uint32_t b0, uint32_t b1) {
    asm volatile("mma.sync.aligned.m16n8k16.row.col.f32.f16.f16.f32 "
                 "{%0,%1,%2,%3},{%4,%5,%6,%7},{%8,%9},{%0,%1,%2,%3};\n"
                 : "+f"(c[0]), "+f"(c[1]), "+f"(c[2]), "+f"(c[3])
                 : "r"(a[0]), "r"(a[1]), "r"(a[2]), "r"(a[3]), "r"(b0), "r"(b1));
}
__device__ __forceinline__ uint32_t pack2(float a, float b, float& ra, float& rb) {
    __half ha = __float2half_rn(a), hb = __float2half_rn(b);
    ra = a - __half2float(ha);
    rb = b - __half2float(hb);
    __half2 p = __halves2half2(ha, hb);
    return *reinterpret_cast<uint32_t*>(&p);
}

// ---------------- W pre-split ----------------
__global__ void __launch_bounds__(256) split_w_kernel(const float* __restrict__ gw,
                                                      const float* __restrict__ nw) {
    int i = blockIdx.x * blockDim.x + threadIdx.x;   // (n, kt, kc, qc)
    if (i >= NN * NKT * 8) return;
    int qc = i & 3, kc = (i >> 2) & 1, kt = (i >> 3) & 63, n = i >> 9;
    const float* src = (n < EN) ? (gw + (size_t)n * BDIM) : (nw + (size_t)(n - EN) * BDIM);
    int kb = kt * BK + kc * 16 + 2 * qc;
    float w0 = src[kb] * WSCALE,     w1 = src[kb + 1] * WSCALE;
    float w2 = src[kb + 8] * WSCALE, w3 = src[kb + 9] * WSCALE;
    float r0, r1, r2, r3;
    uint32_t h01 = pack2(w0, w1, r0, r1);
    uint32_t h23 = pack2(w2, w3, r2, r3);
    float d0, d1;
    uint32_t l01 = pack2(r0, r1, d0, d1);
    uint32_t l23 = pack2(r2, r3, d0, d1);
    g_Wc[(size_t)kt * 1024 + n * 8 + kc * 4 + qc] = make_uint4(h01, h23, l01, l23);
}

// ---------------- fused GEMM + gate ----------------
__global__ void __launch_bounds__(512, 1)
gate_kernel(const float* __restrict__ x, const float* __restrict__ noise,
            float* __restrict__ out) {
    extern __shared__ char smem[];
    const uint32_t sb = smem_u32(smem);
    const int tid  = threadIdx.x;
    const int wid  = tid >> 5, lane = tid & 31;
    const int gr   = lane >> 2, qc = lane & 3;
    const int wm   = wid & 3;          // 4 row groups of 32
    const int wn   = wid >> 2;         // 4 col groups of 32
    const int m0   = blockIdx.x * BM;

    // A staging: this thread stores row ar, k-octet ao (8 fp32 -> 16B fp16)
    const int ar = tid & 127, ao = tid >> 7;
    const float* xrow = x + (size_t)(m0 + ar) * BDIM + ao * 8;
    const uint32_t swoA = SW64((uint32_t)(ar * 64 + ao * 16));

    // ldmatrix addresses (tile-relative, SW64), tm sub-tiles of 16 rows.
    // kc=1 is +32B pre-swizzle; since bit5 of the pre-swizzle base is 0 and the
    // XOR source bits [7:9) are unaffected by +32: SW64(base+32) = SW64(base)^32.
    const int lrow = lane & 15, lko = lane >> 4;
    uint32_t aoff[2];
#pragma unroll
    for (int tm = 0; tm < 2; tm++)
        aoff[tm] = SW64((uint32_t)((32 * wm + 16 * tm + lrow) * 64 + lko * 16));
    // B fragment base: n*192 + qc*16; kc adds 64 (linear); n-tile t adds 1536
    const uint32_t wbase = (uint32_t)((32 * wn + gr) * 192 + qc * 16);

    float acc[2][4][4];
#pragma unroll
    for (int a = 0; a < 2; a++)
#pragma unroll
        for (int b = 0; b < 4; b++)
#pragma unroll
            for (int c = 0; c < 4; c++) acc[a][b][c] = 0.f;

    auto copyW = [&](int kt, uint32_t stage) {
#pragma unroll
        for (int j = 0; j < 2; j++) {
            int id = tid + j * 512;                        // 1024 records
            cp16(stage + ST_W + (id >> 3) * 192 + (id & 7) * 16,
                 (const void*)(g_Wc + (size_t)kt * 1024 + id));
        }
    };
    auto stsA = [&](uint32_t stage, float4 v0, float4 v1) {
        float r0, r1, r2, r3, r4, r5, r6, r7;
        uint32_t h0 = pack2(v0.x, v0.y, r0, r1);
        uint32_t h1 = pack2(v0.z, v0.w, r2, r3);
        uint32_t h2 = pack2(v1.x, v1.y, r4, r5);
        uint32_t h3 = pack2(v1.z, v1.w, r6, r7);
        float d0, d1;
        uint32_t l0 = pack2(r0, r1, d0, d1);
        uint32_t l1 = pack2(r2, r3, d0, d1);
        uint32_t l2 = pack2(r4, r5, d0, d1);
        uint32_t l3 = pack2(r6, r7, d0, d1);
        sts128(stage + ST_AH + swoA, h0, h1, h2, h3);
        sts128(stage + ST_AL + swoA, l0, l1, l2, l3);
    };

    // fragment buffers
    uint32_t a0h[2][4], a0l[2][4], a1h[2][4], a1l[2][4];
    uint32_t bh[4][2], bl[4][2];

#define LDM_A(H, L, stg, kc)                                         \
    do {                                                             \
        ldm4((H)[0], (stg) + ST_AH + (aoff[0] ^ ((kc) * 32)));       \
        ldm4((H)[1], (stg) + ST_AH + (aoff[1] ^ ((kc) * 32)));       \
        ldm4((L)[0], (stg) + ST_AL + (aoff[0] ^ ((kc) * 32)));       \
        ldm4((L)[1], (stg) + ST_AL + (aoff[1] ^ ((kc) * 32)));       \
    } while (0)
#define LDS_B(stg, kc)                                               \
    do {                                                             \
        _Pragma("unroll")                                            \
        for (int t = 0; t < 4; t++) {                                \
            uint32_t r_[4];                                          \
            lds128(r_, (stg) + ST_W + wbase + (kc) * 64 + t * 1536); \
            bh[t][0] = r_[0]; bh[t][1] = r_[1];                      \
            bl[t][0] = r_[2]; bl[t][1] = r_[3];                      \
        }                                                            \
    } while (0)
#define MMA_BURST(H, L)                                        \
    do {                                                       \
        _Pragma("unroll")                                      \
        for (int t = 0; t < 4; t++) {                          \
            mma16(acc[0][t], (H)[0], bh[t][0], bh[t][1]);      \
            mma16(acc[1][t], (H)[1], bh[t][0], bh[t][1]);      \
        }                                                      \
        _Pragma("unroll")                                      \
        for (int t = 0; t < 4; t++) {                          \
            mma16(acc[0][t], (H)[0], bl[t][0], bl[t][1]);      \
            mma16(acc[1][t], (H)[1], bl[t][0], bl[t][1]);      \
        }                                                      \
        _Pragma("unroll")                                      \
        for (int t = 0; t < 4; t++) {                          \
            mma16(acc[0][t], (L)[0], bh[t][0], bh[t][1]);      \
            mma16(acc[1][t], (L)[1], bh[t][0], bh[t][1]);      \
        }                                                      \
    } while (0)

    // ---------------- prolog ----------------
    copyW(0, sb + 0 * STAGE);
    asm volatile("cp.async.commit_group;" ::: "memory");
    copyW(1, sb + 1 * STAGE);
    asm volatile("cp.async.commit_group;" ::: "memory");
    {
        float4 v0 = *(const float4*)(xrow);
        float4 v1 = *(const float4*)(xrow + 4);
        stsA(sb + 0 * STAGE, v0, v1);                      // A(0)
        v0 = *(const float4*)(xrow + BK);
        v1 = *(const float4*)(xrow + BK + 4);
        stsA(sb + 1 * STAGE, v0, v1);                      // A(1)
    }
    float4 xr0 = *(const float4*)(xrow + 2 * BK);          // x(2)
    float4 xr1 = *(const float4*)(xrow + 2 * BK + 4);

    asm volatile("cp.async.wait_group 0;" ::: "memory");   // W(0), W(1) landed
    __syncthreads();
    LDM_A(a0h, a0l, sb + 0 * STAGE, 0);                    // frags(0,0)

    for (int kt = 0; kt < NKT; kt++) {
        const uint32_t stg  = sb + (kt % 3) * STAGE;
        const uint32_t stg1 = sb + ((kt + 1) % 3) * STAGE;
        const uint32_t stg2 = sb + ((kt + 2) % 3) * STAGE;

        if (kt) {
            asm volatile("cp.async.wait_group 1;" ::: "memory");  // W(kt) landed
            __syncthreads();   // all A-STS(kt+1) + W visible; stage kt+2 region free
        }

        // kc = 0: B JIT, prefetch A(kt,1), MMA burst from buffer 0
        LDS_B(stg, 0);
        LDM_A(a1h, a1l, stg, 1);
        MMA_BURST(a0h, a0l);

        // staging for kt+2 (overlaps tensor)
        if (kt + 2 < NKT) {
            stsA(stg2, xr0, xr1);
            copyW(kt + 2, stg2);
        }
        if (kt + 3 < NKT) {
            const float* xp = xrow + (kt + 3) * BK;
            xr0 = *(const float4*)(xp);
            xr1 = *(const float4*)(xp + 4);
        }
        asm volatile("cp.async.commit_group;" ::: "memory");

        // kc = 1: B JIT, prefetch A(kt+1,0) from resident stage, burst buffer 1
        LDS_B(stg, 1);
        if (kt + 1 < NKT) LDM_A(a0h, a0l, stg1, 0);
        MMA_BURST(a1h, a1l);
    }

    // -------- epilogue --------
    __syncthreads();                 // all warps done reading stages
    float* Ls = (float*)smem;        // [128][LLD] logits (reuses stage smem)
#pragma unroll
    for (int tm = 0; tm < 2; tm++) {
        int row0 = 32 * wm + 16 * tm + gr;
#pragma unroll
        for (int t = 0; t < 4; t++) {
            int col0 = 32 * wn + 8 * t + 2 * qc;
            Ls[row0 * LLD + col0]           = acc[tm][t][0] * WSCALE_INV;
            Ls[row0 * LLD + col0 + 1]       = acc[tm][t][1] * WSCALE_INV;
            Ls[(row0 + 8) * LLD + col0]     = acc[tm][t][2] * WSCALE_INV;
            Ls[(row0 + 8) * LLD + col0 + 1] = acc[tm][t][3] * WSCALE_INV;
        }
    }
    // zero this CTA's output block (coalesced) meanwhile
    {
        float4 z = make_float4(0.f, 0.f, 0.f, 0.f);
        float4* ob = (float4*)(out + (size_t)m0 * EN);
#pragma unroll
        for (int i = tid; i < BM * EN / 4; i += 512) ob[i] = z;
    }
    __syncthreads();

    if (tid < BM) {                  // one output row per thread
        const float* Lr = Ls + tid * LLD;
        const float* nz = noise + (size_t)(m0 + tid) * EN;
        float best = -3e38f, second = -3e38f;
        int bi = 0, si = 0;
#pragma unroll 4
        for (int e = 0; e < EN; e++) {
            float z  = Lr[EN + e];
            float sp = fmaxf(z, 0.f) + log1pf(expf(-fabsf(z)));   // accurate softplus
            float w  = Lr[e] + nz[e] * sp;
            if (w > best)        { second = best; si = bi; best = w; bi = e; }
            else if (w > second) { second = w; si = e; }
        }
        float e2  = expf(second - best);
        float inv = 1.f / (1.f + e2);
        float* orow = out + (size_t)(m0 + tid) * EN;
        orow[bi] = inv;
        orow[si] = e2 * inv;
    }
}

extern "C" void kernel_launch(void* const* d_in, const int* in_sizes, int n_in,
                              void* d_out, int out_size) {
    const float* x  = (const float*)d_in[0];
    const float* gw = (const float*)d_in[1];
    const float* nw = (const float*)d_in[2];
    const float* nz = (const float*)d_in[3];
    float* out = (float*)d_out;

    static bool attr_done = false;
    if (!attr_done) {
        cudaFuncSetAttribute(gate_kernel, cudaFuncAttributeMaxDynamicSharedMemorySize,
                             SMEM_TOTAL);
        attr_done = true;
    }

    split_w_kernel<<<(NN * NKT * 8 + 255) / 256, 256>>>(gw, nw);
    gate_kernel<<<16384 / BM, 512, SMEM_TOTAL>>>(x, nz, out);
}